// round 7
// baseline (speedup 1.0000x reference)
#include <cuda_runtime.h>
#include <cuda_fp16.h>
#include <math.h>
#include <stdint.h>

// Problem constants
constexpr int kT  = 2048;
constexpr int kDm = 1024;
constexpr int kDi = 2048;
constexpr int kNL = 4;
constexpr int kNS = 16;
constexpr int kV  = 32000;
constexpr int kXP = 33;

// Scratch (no cudaMalloc allowed). Packed fp16 buffers are tile-major:
// tile = 128 rows x 32 halves (8KB), XOR-swizzled (bits [5:3] ^= row&7).
__device__ float  g_x  [kT * kDm];                     // residual (fp32)
__device__ __align__(16) __half g_xnh[kT * kDm];       // rmsnorm out, packed
__device__ float  g_xz [kT * 2 * kDi];                 // in_proj out
__device__ float  g_u  [kT * kDi];                     // conv+silu out
__device__ float  g_xp [kT * kXP];                     // x_proj out
__device__ __align__(16) __half g_ygh[kT * kDi];       // scan out, packed
__device__ __align__(16) __half g_wh_in [kNL * 2 * kDi * kDm]; // packed 256-row tiles
__device__ __align__(16) __half g_wh_out[kNL * kDm * kDi];     // packed 128-row tiles
__device__ __align__(16) __half g_embh  [kV * kDm];            // packed 256-row tiles

// ---------------------------------------------------------------------------
__device__ __forceinline__ uint32_t smem_u32(const void* p) {
    uint32_t a;
    asm("{ .reg .u64 t; cvta.to.shared.u64 t, %1; cvt.u32.u64 %0, t; }"
        : "=r"(a) : "l"(p));
    return a;
}

#define MBAR_INIT(a, n) \
    asm volatile("mbarrier.init.shared.b64 [%0], %1;" :: "r"(a), "r"(n) : "memory")
#define MBAR_EXPECT_TX(a, tx) \
    asm volatile("mbarrier.arrive.expect_tx.shared.b64 _, [%0], %1;" \
                 :: "r"(a), "r"(tx) : "memory")
#define MBAR_WAIT(a, ph) do {                                                \
    asm volatile(                                                            \
        "{\n\t.reg .pred P;\n"                                               \
        "W%=:\n\t"                                                           \
        "mbarrier.try_wait.parity.acquire.cta.shared::cta.b64 P, [%0], %1, 0x989680;\n\t" \
        "@P bra.uni D%=;\n\t"                                                \
        "bra.uni W%=;\n"                                                     \
        "D%=:\n\t}"                                                          \
        :: "r"(a), "r"(ph) : "memory");                                      \
} while (0)
#define BULK_LD(dst, src, bytes, bar) \
    asm volatile("cp.async.bulk.shared::cluster.global.mbarrier::complete_tx::bytes " \
                 "[%0], [%1], %2, [%3];" \
                 :: "r"(dst), "l"(src), "r"(bytes), "r"(bar) : "memory")

// ---------------------------------------------------------------------------
// Weight pack: f32 [N,K] row-major -> fp16 tiles [nb][kb][R x 32], swizzled.
// ---------------------------------------------------------------------------
template <int R>
__global__ void pack_w_kernel(const float* __restrict__ in,
                              __half* __restrict__ out, int N, int K) {
    long i = (long)blockIdx.x * blockDim.x + threadIdx.x;
    long e = i * 4;
    if (e >= (long)N * K) return;
    int n = (int)(e / K), k = (int)(e % K);
    float4 v = *(const float4*)(in + e);
    int nb = n / R, rr = n % R, kb = k >> 5, col = k & 31;
    int NKt = K >> 5;
    size_t off = ((size_t)(nb * NKt + kb) * (R * 64)) +
                 (uint32_t)((rr * 64 + col * 2) ^ ((rr & 7) << 3));
    __half2 h0 = __floats2half2_rn(v.x, v.y);
    __half2 h1 = __floats2half2_rn(v.z, v.w);
    uint2 u;
    u.x = *(uint32_t*)&h0; u.y = *(uint32_t*)&h1;
    *(uint2*)((char*)out + off) = u;
}

// ---------------------------------------------------------------------------
// Embedding gather (fp32 residual)
// ---------------------------------------------------------------------------
__global__ void embed_kernel(const int* __restrict__ idx,
                             const float* __restrict__ emb) {
    int t = blockIdx.x;
    int row = idx[t];
    const float4* src = (const float4*)(emb + (size_t)row * kDm);
    float4* dst = (float4*)(g_x + (size_t)t * kDm);
    dst[threadIdx.x] = src[threadIdx.x];
}

// ---------------------------------------------------------------------------
// RMSNorm -> packed swizzled fp16 (tile rows 128, K=kDm)
// ---------------------------------------------------------------------------
__global__ void rmsnorm_kernel(const float* __restrict__ in,
                               const float* __restrict__ w,
                               __half* __restrict__ out) {
    __shared__ float red[8];
    __shared__ float s_scale;
    int t = blockIdx.x;
    float4 v = ((const float4*)(in + (size_t)t * kDm))[threadIdx.x];
    float ss = v.x * v.x + v.y * v.y + v.z * v.z + v.w * v.w;
    #pragma unroll
    for (int o = 16; o; o >>= 1) ss += __shfl_xor_sync(0xffffffffu, ss, o);
    int warp = threadIdx.x >> 5, lane = threadIdx.x & 31;
    if (lane == 0) red[warp] = ss;
    __syncthreads();
    if (threadIdx.x == 0) {
        float s = 0.f;
        #pragma unroll
        for (int i = 0; i < 8; i++) s += red[i];
        s_scale = rsqrtf(s / (float)kDm + 1e-5f);
    }
    __syncthreads();
    float sc = s_scale;
    float4 wv = ((const float4*)w)[threadIdx.x];
    __half2 h0 = __floats2half2_rn(v.x * sc * wv.x, v.y * sc * wv.y);
    __half2 h1 = __floats2half2_rn(v.z * sc * wv.z, v.w * sc * wv.w);
    // packed address: d0 = 4*tid
    int d0 = threadIdx.x * 4;
    int tb = t >> 7, r = t & 127, kb = d0 >> 5, col = d0 & 31;
    const int NKt = kDm >> 5;   // 32
    size_t off = ((size_t)(tb * NKt + kb) * 8192) +
                 (uint32_t)((r * 64 + col * 2) ^ ((r & 7) << 3));
    uint2 u;
    u.x = *(uint32_t*)&h0; u.y = *(uint32_t*)&h1;
    *(uint2*)((char*)out + off) = u;
}

// ---------------------------------------------------------------------------
// fp16 mma.sync NT GEMM with cp.async.bulk pipeline.
// A packed 128-row tiles; B packed BN-row tiles (both 32-half k-chunks,
// swizzled). C fp32 row-major [M, N] (+= if acc_flag).
// BM=128, BN in {256,128}; THREADS = 2 * (BN/32) warps * 32.
// Warp grid 2(m) x BN/32(n); warp tile 64x32; m16n8k16.f16 fp32-accum.
// ---------------------------------------------------------------------------
template <int BN, int THREADS>
__global__ __launch_bounds__(THREADS, (BN == 128) ? 2 : 1)
void gemm_bulk(const __half* __restrict__ Ap, const __half* __restrict__ Bp,
               float* __restrict__ C, int M, int N, int K, int acc_flag) {
    constexpr int S  = 3;
    constexpr int SB = 8192 + BN * 64;        // stage bytes (A tile + B tile)
    constexpr int WNN = BN / 32;              // warps along n
    extern __shared__ char sm[];
    uint32_t sb = smem_u32(sm);               // [0..64): mbarriers; bufs at 1024

    int tid = threadIdx.x, lane = tid & 31, wrp = tid >> 5;
    int wm = wrp / WNN, wn = wrp % WNN;
    int l2 = lane & 3, l4 = lane >> 2;
    int NKt = K >> 5;

    const char* gA = (const char*)Ap + (size_t)blockIdx.y * NKt * 8192;
    const char* gB = (const char*)Bp + (size_t)blockIdx.x * NKt * (BN * 64);

    if (tid == 0) {
        #pragma unroll
        for (int s = 0; s < S; s++) MBAR_INIT(sb + 8 * s, 1);
    }
    __syncthreads();

    auto issue = [&](int j) {
        uint32_t bar = sb + 8 * (j % S);
        uint32_t dA  = sb + 1024 + (j % S) * SB;
        MBAR_EXPECT_TX(bar, (uint32_t)SB);
        BULK_LD(dA, gA + (size_t)j * 8192, 8192u, bar);
        BULK_LD(dA + 8192, gB + (size_t)j * (BN * 64), (uint32_t)(BN * 64), bar);
    };
    if (tid == 0) { issue(0); issue(1); }

    float acc[4][4][4];
    #pragma unroll
    for (int i = 0; i < 4; i++)
        #pragma unroll
        for (int j = 0; j < 4; j++)
            #pragma unroll
            for (int r = 0; r < 4; r++) acc[i][j][r] = 0.f;

    // Pre-swizzled column byte offsets for the 4 k-sub-chunks (8 halves each)
    uint32_t cx[4];
    #pragma unroll
    for (int p = 0; p < 4; p++) cx[p] = (uint32_t)((p * 16 + 4 * l2) ^ (l4 << 3));

    for (int ks = 0; ks < NKt; ks++) {
        MBAR_WAIT(sb + 8 * (ks % S), (ks / S) & 1);

        const char* As = sm + 1024 + (ks % S) * SB;
        const char* Bs = As + 8192;
        #pragma unroll
        for (int ph = 0; ph < 2; ph++) {       // k16 phases
            uint32_t af[4][4];
            uint32_t bf[4][2];
            #pragma unroll
            for (int mi = 0; mi < 4; mi++) {
                uint32_t rb = (uint32_t)(wm * 64 + mi * 16 + l4) * 64;
                af[mi][0] = *(const uint32_t*)(As + rb       + cx[ph * 2]);
                af[mi][1] = *(const uint32_t*)(As + rb + 512 + cx[ph * 2]);
                af[mi][2] = *(const uint32_t*)(As + rb       + cx[ph * 2 + 1]);
                af[mi][3] = *(const uint32_t*)(As + rb + 512 + cx[ph * 2 + 1]);
            }
            #pragma unroll
            for (int ni = 0; ni < 4; ni++) {
                uint32_t rb = (uint32_t)(wn * 32 + ni * 8 + l4) * 64;
                bf[ni][0] = *(const uint32_t*)(Bs + rb + cx[ph * 2]);
                bf[ni][1] = *(const uint32_t*)(Bs + rb + cx[ph * 2 + 1]);
            }
            #pragma unroll
            for (int mi = 0; mi < 4; mi++)
                #pragma unroll
                for (int ni = 0; ni < 4; ni++) {
                    asm volatile(
                        "mma.sync.aligned.m16n8k16.row.col.f32.f16.f16.f32 "
                        "{%0,%1,%2,%3}, {%4,%5,%6,%7}, {%8,%9}, {%0,%1,%2,%3};"
                        : "+f"(acc[mi][ni][0]), "+f"(acc[mi][ni][1]),
                          "+f"(acc[mi][ni][2]), "+f"(acc[mi][ni][3])
                        : "r"(af[mi][0]), "r"(af[mi][1]),
                          "r"(af[mi][2]), "r"(af[mi][3]),
                          "r"(bf[ni][0]), "r"(bf[ni][1]));
                }
        }
        __syncthreads();
        if (tid == 0 && ks + 2 < NKt) issue(ks + 2);
    }

    // Epilogue
    #pragma unroll
    for (int mi = 0; mi < 4; mi++) {
        int row0 = blockIdx.y * 128 + wm * 64 + mi * 16 + l4;
        #pragma unroll
        for (int ni = 0; ni < 4; ni++) {
            int col0 = blockIdx.x * BN + wn * 32 + ni * 8 + 2 * l2;
            float2* p0 = (float2*)(C + (size_t)row0 * N + col0);
            float2* p1 = (float2*)(C + (size_t)(row0 + 8) * N + col0);
            if (acc_flag) {
                float2 v0 = *p0, v1 = *p1;
                v0.x += acc[mi][ni][0]; v0.y += acc[mi][ni][1];
                v1.x += acc[mi][ni][2]; v1.y += acc[mi][ni][3];
                *p0 = v0; *p1 = v1;
            } else {
                *p0 = make_float2(acc[mi][ni][0], acc[mi][ni][1]);
                *p1 = make_float2(acc[mi][ni][2], acc[mi][ni][3]);
            }
        }
    }
}

constexpr int SMEM_BN256 = 1024 + 3 * (8192 + 256 * 64);   // 74752
constexpr int SMEM_BN128 = 1024 + 3 * (8192 + 128 * 64);   // 50176

// ---------------------------------------------------------------------------
// Causal depthwise conv (K=4) + bias + silu
// ---------------------------------------------------------------------------
__global__ void conv_silu_kernel(const float* __restrict__ cw,
                                 const float* __restrict__ cb) {
    int i = blockIdx.x * blockDim.x + threadIdx.x;
    int t = i / kDi, c = i - t * kDi;
    float w0 = cw[c * 4 + 0], w1 = cw[c * 4 + 1];
    float w2 = cw[c * 4 + 2], w3 = cw[c * 4 + 3];
    const int stride = 2 * kDi;
    float s = cb[c];
    if (t >= 3) s += w0 * g_xz[(size_t)(t - 3) * stride + c];
    if (t >= 2) s += w1 * g_xz[(size_t)(t - 2) * stride + c];
    if (t >= 1) s += w2 * g_xz[(size_t)(t - 1) * stride + c];
    s += w3 * g_xz[(size_t)t * stride + c];
    g_u[i] = s / (1.f + __expf(-s));
}

// ---------------------------------------------------------------------------
// x_proj
// ---------------------------------------------------------------------------
__global__ void xproj_kernel(const float* __restrict__ W) {
    int t = blockIdx.x;
    int warp = threadIdx.x >> 5, lane = threadIdx.x & 31;
    const float4* ur = (const float4*)(g_u + (size_t)t * kDi);
    for (int j = warp; j < kXP; j += 8) {
        const float4* wr = (const float4*)(W + (size_t)j * kDi);
        float s = 0.f;
        #pragma unroll 4
        for (int k = lane; k < kDi / 4; k += 32) {
            float4 a = ur[k], b = wr[k];
            s += a.x * b.x + a.y * b.y + a.z * b.z + a.w * b.w;
        }
        #pragma unroll
        for (int o = 16; o; o >>= 1) s += __shfl_xor_sync(0xffffffffu, s, o);
        if (lane == 0) g_xp[t * kXP + j] = s;
    }
}

// ---------------------------------------------------------------------------
// Selective scan -> packed swizzled fp16 (tile rows 128, K=kDi)
// ---------------------------------------------------------------------------
__global__ void scan_kernel(const float* __restrict__ A_log,
                            const float* __restrict__ dtw_,
                            const float* __restrict__ dtb_,
                            const float* __restrict__ Dp_) {
    int tid = threadIdx.x;
    int n = tid & 15;
    int g = tid >> 4;
    int d = blockIdx.x * 8 + g;
    float a   = -expf(A_log[(size_t)d * kNS + n]);
    float dtw = dtw_[d];
    float dtb = dtb_[d];
    float Dp  = Dp_[d];
    const int NKt = kDi >> 5;   // 64
    int kb = d >> 5, col = d & 31;
    float h = 0.f;
    for (int t = 0; t < kT; t++) {
        const float* xpr = g_xp + (size_t)t * kXP;
        float dtr = xpr[0];
        float xv = dtr * dtw + dtb;
        float dt = (xv > 20.f) ? xv : log1pf(__expf(xv));
        float Bn = xpr[1 + n];
        float Cn = xpr[17 + n];
        float ut = g_u[(size_t)t * kDi + d];
        float dA = __expf(dt * a);
        h = dA * h + (dt * ut) * Bn;
        float p = h * Cn;
        p += __shfl_xor_sync(0xffffffffu, p, 8);
        p += __shfl_xor_sync(0xffffffffu, p, 4);
        p += __shfl_xor_sync(0xffffffffu, p, 2);
        p += __shfl_xor_sync(0xffffffffu, p, 1);
        if (n == 0) {
            float z = g_xz[(size_t)t * (2 * kDi) + kDi + d];
            float y = p + ut * Dp;
            int tb = t >> 7, r = t & 127;
            size_t off = ((size_t)(tb * NKt + kb) * 8192) +
                         (uint32_t)((r * 64 + col * 2) ^ ((r & 7) << 3));
            *(__half*)((char*)g_ygh + off) =
                __float2half_rn(y * (z / (1.f + __expf(-z))));
        }
    }
}

// ---------------------------------------------------------------------------
// Host launcher
// ---------------------------------------------------------------------------
extern "C" void kernel_launch(void* const* d_in, const int* in_sizes, int n_in,
                              void* d_out, int out_size) {
    const int*   idx        = (const int*)  d_in[0];
    const float* emb        = (const float*)d_in[1];
    const float* norm_w     = (const float*)d_in[2];
    const float* in_proj_w  = (const float*)d_in[3];
    const float* conv_w     = (const float*)d_in[4];
    const float* conv_b     = (const float*)d_in[5];
    const float* x_proj_w   = (const float*)d_in[6];
    const float* dt_proj_w  = (const float*)d_in[7];
    const float* dt_proj_b  = (const float*)d_in[8];
    const float* A_log      = (const float*)d_in[9];
    const float* D_param    = (const float*)d_in[10];
    const float* out_proj_w = (const float*)d_in[11];
    const float* norm_f_w   = (const float*)d_in[12];
    float* out = (float*)d_out;

    float *x, *xz;
    __half *xnh, *ygh, *wh_in, *wh_out, *embh;
    cudaGetSymbolAddress((void**)&x,      g_x);
    cudaGetSymbolAddress((void**)&xnh,    g_xnh);
    cudaGetSymbolAddress((void**)&xz,     g_xz);
    cudaGetSymbolAddress((void**)&ygh,    g_ygh);
    cudaGetSymbolAddress((void**)&wh_in,  g_wh_in);
    cudaGetSymbolAddress((void**)&wh_out, g_wh_out);
    cudaGetSymbolAddress((void**)&embh,   g_embh);

    cudaFuncSetAttribute(gemm_bulk<256, 512>,
                         cudaFuncAttributeMaxDynamicSharedMemorySize, SMEM_BN256);
    cudaFuncSetAttribute(gemm_bulk<128, 256>,
                         cudaFuncAttributeMaxDynamicSharedMemorySize, SMEM_BN128);

    // Convert + pack weights (every launch; deterministic)
    {
        long n1 = (long)kNL * 2 * kDi * kDm / 4;
        long n2 = (long)kNL * kDm * kDi / 4;
        long n3 = (long)kV * kDm / 4;
        pack_w_kernel<256><<<(int)((n1 + 255) / 256), 256>>>(in_proj_w,  wh_in,
                                                             kNL * 2 * kDi, kDm);
        pack_w_kernel<128><<<(int)((n2 + 255) / 256), 256>>>(out_proj_w, wh_out,
                                                             kNL * kDm, kDi);
        pack_w_kernel<256><<<(int)((n3 + 255) / 256), 256>>>(emb,        embh,
                                                             kV, kDm);
    }

    embed_kernel<<<kT, 256>>>(idx, emb);

    for (int l = 0; l < kNL; l++) {
        rmsnorm_kernel<<<kT, 256>>>(x, norm_w + (size_t)l * kDm, xnh);
        gemm_bulk<256, 512><<<dim3(2 * kDi / 256, kT / 128), 512, SMEM_BN256>>>(
            xnh, wh_in + (size_t)l * 2 * kDi * kDm, xz, kT, 2 * kDi, kDm, 0);
        conv_silu_kernel<<<kT * kDi / 256, 256>>>(
            conv_w + (size_t)l * kDi * 4, conv_b + (size_t)l * kDi);
        xproj_kernel<<<kT, 256>>>(x_proj_w + (size_t)l * kXP * kDi);
        scan_kernel<<<kDi / 8, 128>>>(
            A_log + (size_t)l * kDi * kNS,
            dt_proj_w + (size_t)l * kDi,
            dt_proj_b + (size_t)l * kDi,
            D_param + (size_t)l * kDi);
        gemm_bulk<128, 256><<<dim3(kDm / 128, kT / 128), 256, SMEM_BN128>>>(
            ygh, wh_out + (size_t)l * kDm * kDi, x, kT, kDm, kDi, 1);
    }

    rmsnorm_kernel<<<kT, 256>>>(x, norm_f_w, xnh);
    gemm_bulk<256, 512><<<dim3(kV / 256, kT / 128), 512, SMEM_BN256>>>(
        xnh, embh, out, kT, kV, kDm, 0);
}